// round 9
// baseline (speedup 1.0000x reference)
#include <cuda_runtime.h>
#include <cstdint>
#include <math.h>

// ============================================================================
// CRF token loss: B=512, T=2048, L=37.  loss = -(sum_b num_b - denom_b)/n_tok
// R8: chunked forward (contraction warm-up) with TWO chains per warp sharing
// one register copy of M (the 76-reg hog that killed R7 occupancy).
// 2048 warps, __launch_bounds__(128,3) -> 3 warps/SMSP = 6 chains/SMSP.
// Lane owns a column pair; q duplicated in smem so LDS.128 feeds fma.f32x2.
// ============================================================================

#define LSTATE 37
#define TLEN   2048
#define BATCH  512
#define NCH    8
#define CSTEP  256
#define WARM   32
#define PF     4
#define NGROUPS ((WARM + CSTEP) / PF)   // 72
#define WARMG   (WARM / PF)             // 8
#define FULLMASK 0xffffffffu

__device__ __align__(16) float2 g_Mcp[19 * 38]; // [k][i]=(e^T[i][2k], e^T[i][2k+1])
__device__ float g_num[BATCH];
__device__ int   g_msum[BATCH];
__device__ float g_chunk[BATCH * NCH];
__device__ int   g_done;

// ---- f32x2 helpers ---------------------------------------------------------
__device__ __forceinline__ void fma2(unsigned long long& acc,
                                     unsigned long long a, unsigned long long b) {
    asm("fma.rn.f32x2 %0, %1, %2, %0;" : "+l"(acc) : "l"(a), "l"(b));
}
__device__ __forceinline__ unsigned long long add2(unsigned long long a,
                                                   unsigned long long b) {
    unsigned long long c;
    asm("add.rn.f32x2 %0, %1, %2;" : "=l"(c) : "l"(a), "l"(b));
    return c;
}
__device__ __forceinline__ unsigned long long mul2(unsigned long long a,
                                                   unsigned long long b) {
    unsigned long long c;
    asm("mul.rn.f32x2 %0, %1, %2;" : "=l"(c) : "l"(a), "l"(b));
    return c;
}
__device__ __forceinline__ float lo32(unsigned long long v) {
    return __uint_as_float((unsigned)v);
}
__device__ __forceinline__ float hi32(unsigned long long v) {
    return __uint_as_float((unsigned)(v >> 32));
}
__device__ __forceinline__ unsigned long long pack2(float lo, float hi) {
    return (unsigned long long)__float_as_uint(lo)
         | ((unsigned long long)__float_as_uint(hi) << 32);
}

// ---------------------------------------------------------------------------
// Kernel 1: numerator, one block per batch; block 0 also preps M pairs
// ---------------------------------------------------------------------------
__global__ void num_kernel(const float* __restrict__ em,
                           const float* __restrict__ trans,
                           const float* __restrict__ startt,
                           const float* __restrict__ endt,
                           const int*   __restrict__ labels,
                           const int*   __restrict__ mask) {
    int b = blockIdx.x, tid = threadIdx.x;
    if (b == 0) {
        for (int x = tid; x < 19 * 38; x += 256) {
            int k = x / 38, i = x % 38;
            float lo = 0.0f, hi = 0.0f;
            if (i < LSTATE) {
                lo = expf(trans[i * LSTATE + 2 * k]);
                if (2 * k + 1 < LSTATE) hi = expf(trans[i * LSTATE + 2 * k + 1]);
            }
            g_Mcp[x] = make_float2(lo, hi);
        }
        if (tid == 0) g_done = 0;
    }

    __shared__ float sacc[8];
    __shared__ int   snt[8];
    const int*   lb = labels + (size_t)b * TLEN;
    const int*   mk = mask   + (size_t)b * TLEN;
    const float* eb = em     + (size_t)b * TLEN * LSTATE;

    float acc = 0.0f; int msum = 0;
    for (int t = tid; t < TLEN; t += 256) {
        int lt = lb[t]; int m = mk[t]; msum += m;
        if (t == 0) acc += startt[lt] + eb[lt];
        else if (m) acc += trans[lb[t - 1] * LSTATE + lt]
                         + eb[(size_t)t * LSTATE + lt];
    }
    int lane = tid & 31, wid = tid >> 5;
    #pragma unroll
    for (int o = 16; o; o >>= 1) {
        acc  += __shfl_xor_sync(FULLMASK, acc,  o);
        msum += __shfl_xor_sync(FULLMASK, msum, o);
    }
    if (lane == 0) { sacc[wid] = acc; snt[wid] = msum; }
    __syncthreads();
    if (tid == 0) {
        float a = 0.0f; int n = 0;
        #pragma unroll
        for (int k = 0; k < 8; k++) { a += sacc[k]; n += snt[k]; }
        g_num[b]  = a + endt[lb[n - 1]];
        g_msum[b] = n;
    }
}

// ---------------------------------------------------------------------------
// Kernel 2: chunked forward. One warp per chunk PAIR (2 chains share M regs).
// 4 warps per block, 512 blocks.
// ---------------------------------------------------------------------------
__global__ void __launch_bounds__(128, 3)
fwd_kernel(const float* __restrict__ em,
           const float* __restrict__ startt,
           const float* __restrict__ endt,
           const int*   __restrict__ mask,
           float* __restrict__ out) {
    __shared__ __align__(16) float dup[4][2][80];   // [warp][chain][dup q]
    __shared__ float fr[4];
    __shared__ int   fn[4];
    __shared__ int   isLast;

    int tid  = threadIdx.x;
    int lane = tid & 31;
    int w    = tid >> 5;
    int wt   = blockIdx.x * 4 + w;      // 0..2047
    int b    = wt >> 2;
    int cA   = (wt & 3) * 2;            // even chunk
    int cB   = cA + 1;                  // odd chunk

    const float* eb = em   + (size_t)b * TLEN * LSTATE;
    const int*   mk = mask + (size_t)b * TLEN;

    int  kc    = (lane < 19) ? lane : 18;
    bool act   = (lane < 19);
    int  col0  = 2 * kc;
    bool hasHi = (2 * kc + 1 < LSTATE);
    int  col1  = hasHi ? (2 * kc + 1) : col0;

    // shared-by-both-chains M column pair (38 i-entries as f32x2)
    unsigned long long Mc[38];
    {
        const unsigned long long* gm = (const unsigned long long*)g_Mcp + kc * 38;
        #pragma unroll
        for (int i = 0; i < 38; i++) Mc[i] = gm[i];
    }

    float* qa = dup[w][0];
    float* qb = dup[w][1];

    // chain inits (cA==0 starts exact from Q0; all others uniform)
    float aLo, aHi;
    if (cA == 0) {
        aLo = expf(startt[col0] + eb[col0]);
        aHi = hasHi ? expf(startt[col1] + eb[col1]) : 0.0f;
    } else {
        aLo = 1.0f; aHi = hasHi ? 1.0f : 0.0f;
    }
    float bLo = 1.0f, bHi = hasHi ? 1.0f : 0.0f;
    if (act) {
        *(float4*)(qa + 4 * kc) = make_float4(aLo, aLo, aHi, aHi);
        *(float4*)(qb + 4 * kc) = make_float4(bLo, bLo, bHi, bHi);
    }

    int t0a = cA * CSTEP - (WARM - 1);   // may be <= 0 for cA==0 (masked)
    int t0b = cB * CSTEP - (WARM - 1);

    // PF-deep prefetch: exp(emission pair) + mask, both chains
    unsigned long long eea[PF], eeb[PF];
    int mma[PF], mmb[PF];
    #pragma unroll
    for (int d = 0; d < PF; d++) {
        int ta = t0a + d;
        int tca = ta < 0 ? 0 : (ta >= TLEN ? TLEN - 1 : ta);
        float a0 = __expf(eb[(size_t)tca * LSTATE + col0]);
        float a1 = hasHi ? __expf(eb[(size_t)tca * LSTATE + col1]) : 0.0f;
        eea[d] = pack2(a0, a1);
        mma[d] = (ta >= 1 && ta < TLEN) ? mk[ta] : 0;

        int tb = t0b + d;
        int tcb = tb >= TLEN ? TLEN - 1 : tb;
        float b0 = __expf(eb[(size_t)tcb * LSTATE + col0]);
        float b1 = hasHi ? __expf(eb[(size_t)tcb * LSTATE + col1]) : 0.0f;
        eeb[d] = pack2(b0, b1);
        mmb[d] = (tb >= 1 && tb < TLEN) ? mk[tb] : 0;
    }

    int   kta = 0, ktb = 0;
    float subA = 0.0f, subB = 0.0f;
    __syncwarp();

    for (int g = 0; g < NGROUPS; g++) {
        if (g == WARMG) {   // record warm-boundary reference (no ktot reset)
            float va = act ? (aLo + aHi) : 0.0f;
            float vb = act ? (bLo + bHi) : 0.0f;
            #pragma unroll
            for (int o = 16; o; o >>= 1) {
                va += __shfl_xor_sync(FULLMASK, va, o);
                vb += __shfl_xor_sync(FULLMASK, vb, o);
            }
            subA = (cA == 0) ? 0.0f
                 : (float)((double)kta * 0.6931471805599453) + logf(va);
            subB = (float)((double)ktb * 0.6931471805599453) + logf(vb);
        }
        #pragma unroll
        for (int u = 0; u < PF; u++) {
            unsigned long long ecA = eea[u], ecB = eeb[u];
            int mcA = mma[u], mcB = mmb[u];
            {   // refill prefetch (off critical path)
                int ta = t0a + g * PF + u + PF;
                int tca = ta < 0 ? 0 : (ta >= TLEN ? TLEN - 1 : ta);
                float a0 = __expf(eb[(size_t)tca * LSTATE + col0]);
                float a1 = hasHi ? __expf(eb[(size_t)tca * LSTATE + col1]) : 0.0f;
                eea[u] = pack2(a0, a1);
                mma[u] = (ta >= 1 && ta < TLEN) ? mk[ta] : 0;

                int tb = t0b + g * PF + u + PF;
                int tcb = tb >= TLEN ? TLEN - 1 : tb;
                float b0 = __expf(eb[(size_t)tcb * LSTATE + col0]);
                float b1 = hasHi ? __expf(eb[(size_t)tcb * LSTATE + col1]) : 0.0f;
                eeb[u] = pack2(b0, b1);
                mmb[u] = (tb >= 1 && tb < TLEN) ? mk[tb] : 0;
            }

            __syncwarp();   // previous stores of both chains visible

            // ---- chain A matvec ----
            {
                const ulonglong2* q16 = (const ulonglong2*)qa;
                ulonglong2 p0 = q16[0];
                unsigned long long x0 = 0, x1 = 0, x2 = 0, x3 = 0;
                fma2(x0, p0.x, Mc[0]);
                fma2(x1, p0.y, Mc[1]);
                #pragma unroll
                for (int k = 1; k < 19; k++) {
                    ulonglong2 p = q16[k];
                    if (k & 1) { fma2(x2, p.x, Mc[2*k]); fma2(x3, p.y, Mc[2*k+1]); }
                    else       { fma2(x0, p.x, Mc[2*k]); fma2(x1, p.y, Mc[2*k+1]); }
                }
                unsigned long long sc = add2(add2(x0, x1), add2(x2, x3));
                unsigned long long qe = mul2(sc, ecA);
                float nLo = mcA ? lo32(qe) : aLo;
                float nHi = mcA ? hi32(qe) : aHi;
                if (u == PF - 1) {   // renorm every PF steps (exact pow-2)
                    float q0 = lo32(p0.x);
                    unsigned eb_ = (__float_as_uint(q0) >> 23) & 0xffu;
                    float scale = __uint_as_float((254u - eb_) << 23);
                    kta += (int)eb_ - 127;
                    nLo *= scale; nHi *= scale;
                }
                aLo = nLo; aHi = nHi;
            }
            // ---- chain B matvec ----
            {
                const ulonglong2* q16 = (const ulonglong2*)qb;
                ulonglong2 p0 = q16[0];
                unsigned long long x0 = 0, x1 = 0, x2 = 0, x3 = 0;
                fma2(x0, p0.x, Mc[0]);
                fma2(x1, p0.y, Mc[1]);
                #pragma unroll
                for (int k = 1; k < 19; k++) {
                    ulonglong2 p = q16[k];
                    if (k & 1) { fma2(x2, p.x, Mc[2*k]); fma2(x3, p.y, Mc[2*k+1]); }
                    else       { fma2(x0, p.x, Mc[2*k]); fma2(x1, p.y, Mc[2*k+1]); }
                }
                unsigned long long sc = add2(add2(x0, x1), add2(x2, x3));
                unsigned long long qe = mul2(sc, ecB);
                float nLo = mcB ? lo32(qe) : bLo;
                float nHi = mcB ? hi32(qe) : bHi;
                if (u == PF - 1) {
                    float q0 = lo32(p0.x);
                    unsigned eb_ = (__float_as_uint(q0) >> 23) & 0xffu;
                    float scale = __uint_as_float((254u - eb_) << 23);
                    ktb += (int)eb_ - 127;
                    nLo *= scale; nHi *= scale;
                }
                bLo = nLo; bHi = nHi;
            }
            if (act) {
                *(float4*)(qa + 4 * kc) = make_float4(aLo, aLo, aHi, aHi);
                *(float4*)(qb + 4 * kc) = make_float4(bLo, bLo, bHi, bHi);
            }
        }
    }

    // chunk contributions: ktot*ln2 + log S_end - sub
    {
        float va, vb;
        va = act ? (aLo + aHi) : 0.0f;                   // cA is even, never 7
        if (cB == NCH - 1)
            vb = act ? (bLo * expf(endt[col0])
                        + (hasHi ? bHi * expf(endt[col1]) : 0.0f)) : 0.0f;
        else
            vb = act ? (bLo + bHi) : 0.0f;
        #pragma unroll
        for (int o = 16; o; o >>= 1) {
            va += __shfl_xor_sync(FULLMASK, va, o);
            vb += __shfl_xor_sync(FULLMASK, vb, o);
        }
        if (lane == 0) {
            g_chunk[b * NCH + cA] =
                (float)((double)kta * 0.6931471805599453) + logf(va) - subA;
            g_chunk[b * NCH + cB] =
                (float)((double)ktb * 0.6931471805599453) + logf(vb) - subB;
        }
    }

    // ---- fused finish: last block reduces everything ----
    __threadfence();
    __syncthreads();
    if (tid == 0)
        isLast = (atomicAdd(&g_done, 1) == (int)gridDim.x - 1);
    __syncthreads();

    if (isLast) {
        __threadfence();
        float acc = 0.0f; int nt = 0;
        for (int i = tid; i < BATCH; i += 128) {
            float d = 0.0f;
            #pragma unroll
            for (int cc = 0; cc < NCH; cc++) d += g_chunk[i * NCH + cc];
            acc += g_num[i] - d;
            nt  += g_msum[i];
        }
        #pragma unroll
        for (int o = 16; o; o >>= 1) {
            acc += __shfl_xor_sync(FULLMASK, acc, o);
            nt  += __shfl_xor_sync(FULLMASK, nt,  o);
        }
        if (lane == 0) { fr[w] = acc; fn[w] = nt; }
        __syncthreads();
        if (tid == 0) {
            float tot = fr[0] + fr[1] + fr[2] + fr[3];
            int   n   = fn[0] + fn[1] + fn[2] + fn[3];
            if (n < 1) n = 1;
            out[0] = -tot / (float)n;
        }
    }
}

// ---------------------------------------------------------------------------
// Launch
// ---------------------------------------------------------------------------
extern "C" void kernel_launch(void* const* d_in, const int* in_sizes, int n_in,
                              void* d_out, int out_size) {
    const float* em     = (const float*)d_in[0];   // emissions [512,2048,37]
    const float* trans  = (const float*)d_in[1];   // transitions [37,37]
    const float* startt = (const float*)d_in[2];   // start_transitions [37]
    const float* endt   = (const float*)d_in[3];   // end_transitions [37]
    const int*   labels = (const int*)d_in[4];     // labels [512,2048]
    const int*   mask   = (const int*)d_in[5];     // attention_mask [512,2048]

    num_kernel<<<BATCH, 256>>>(em, trans, startt, endt, labels, mask);
    fwd_kernel<<<BATCH * NCH / 8, 128>>>(em, startt, endt, mask, (float*)d_out);
}

// round 10
// speedup vs baseline: 1.2488x; 1.2488x over previous
#include <cuda_runtime.h>
#include <cstdint>
#include <math.h>

// ============================================================================
// CRF token loss: B=512, T=2048, L=37.  loss = -(sum_b num_b - denom_b)/n_tok
// R9: chunked forward (contraction warm-up, verified R8) with the smem
// crossbar traffic cut ~2.7x: q read once per chain as 19-lane-predicated
// LDS.128 pairs (M packed as i-pairs, two columns per lane), double-buffered.
// 2048 warps; 2 chains/warp share one 76-reg M copy.
// ============================================================================

#define LSTATE 37
#define TLEN   2048
#define BATCH  512
#define NCH    8
#define CSTEP  256
#define WARM   16
#define PF     4
#define NGROUPS ((WARM + CSTEP) / PF)   // 68
#define WARMG   (WARM / PF)             // 4
#define FULLMASK 0xffffffffu

// g_Mcol[j][i2] = ( exp(T[2*i2][j]), exp(T[2*i2+1][j]) ), col 37 = zeros,
// i2=18 hi-component = 0 (row 37 padding).
__device__ __align__(16) float2 g_Mcol[38 * 19];
__device__ float g_num[BATCH];
__device__ int   g_msum[BATCH];
__device__ float g_chunk[BATCH * NCH];
__device__ int   g_done;

// ---- f32x2 helpers ---------------------------------------------------------
__device__ __forceinline__ void fma2(unsigned long long& acc,
                                     unsigned long long a, unsigned long long b) {
    asm("fma.rn.f32x2 %0, %1, %2, %0;" : "+l"(acc) : "l"(a), "l"(b));
}
__device__ __forceinline__ unsigned long long add2(unsigned long long a,
                                                   unsigned long long b) {
    unsigned long long c;
    asm("add.rn.f32x2 %0, %1, %2;" : "=l"(c) : "l"(a), "l"(b));
    return c;
}
__device__ __forceinline__ float lo32(unsigned long long v) {
    return __uint_as_float((unsigned)v);
}
__device__ __forceinline__ float hi32(unsigned long long v) {
    return __uint_as_float((unsigned)(v >> 32));
}

// ---------------------------------------------------------------------------
// Kernel 1: numerator, one block per batch; block 0 also preps M columns
// ---------------------------------------------------------------------------
__global__ void num_kernel(const float* __restrict__ em,
                           const float* __restrict__ trans,
                           const float* __restrict__ startt,
                           const float* __restrict__ endt,
                           const int*   __restrict__ labels,
                           const int*   __restrict__ mask) {
    int b = blockIdx.x, tid = threadIdx.x;
    if (b == 0) {
        for (int x = tid; x < 38 * 19; x += 256) {
            int j = x / 19, i2 = x % 19;
            float lo = 0.0f, hi = 0.0f;
            if (j < LSTATE) {
                lo = expf(trans[(2 * i2) * LSTATE + j]);
                if (2 * i2 + 1 < LSTATE)
                    hi = expf(trans[(2 * i2 + 1) * LSTATE + j]);
            }
            g_Mcol[x] = make_float2(lo, hi);
        }
        if (tid == 0) g_done = 0;
    }

    __shared__ float sacc[8];
    __shared__ int   snt[8];
    const int*   lb = labels + (size_t)b * TLEN;
    const int*   mk = mask   + (size_t)b * TLEN;
    const float* eb = em     + (size_t)b * TLEN * LSTATE;

    float acc = 0.0f; int msum = 0;
    for (int t = tid; t < TLEN; t += 256) {
        int lt = lb[t]; int m = mk[t]; msum += m;
        if (t == 0) acc += startt[lt] + eb[lt];
        else if (m) acc += trans[lb[t - 1] * LSTATE + lt]
                         + eb[(size_t)t * LSTATE + lt];
    }
    int lane = tid & 31, wid = tid >> 5;
    #pragma unroll
    for (int o = 16; o; o >>= 1) {
        acc  += __shfl_xor_sync(FULLMASK, acc,  o);
        msum += __shfl_xor_sync(FULLMASK, msum, o);
    }
    if (lane == 0) { sacc[wid] = acc; snt[wid] = msum; }
    __syncthreads();
    if (tid == 0) {
        float a = 0.0f; int n = 0;
        #pragma unroll
        for (int k = 0; k < 8; k++) { a += sacc[k]; n += snt[k]; }
        g_num[b]  = a + endt[lb[n - 1]];
        g_msum[b] = n;
    }
}

// ---------------------------------------------------------------------------
// Kernel 2: chunked forward. One warp per chunk pair; 4 warps/block.
// ---------------------------------------------------------------------------
__global__ void __launch_bounds__(128, 3)
fwd_kernel(const float* __restrict__ em,
           const float* __restrict__ startt,
           const float* __restrict__ endt,
           const int*   __restrict__ mask,
           float* __restrict__ out) {
    __shared__ __align__(16) float qsm[4][2][2][40]; // [warp][chain][parity][40]
    __shared__ float fr[4];
    __shared__ int   fn[4];
    __shared__ int   isLast;

    int tid  = threadIdx.x;
    int lane = tid & 31;
    int w    = tid >> 5;
    int wt   = blockIdx.x * 4 + w;      // 0..2047
    int b    = wt >> 2;
    int cA   = (wt & 3) * 2;
    int cB   = cA + 1;

    const float* eb = em   + (size_t)b * TLEN * LSTATE;
    const int*   mk = mask + (size_t)b * TLEN;

    bool act   = (lane < 19);
    int  kc    = act ? lane : 18;
    int  col0  = 2 * kc;
    bool hasHi = (2 * kc + 1 < LSTATE);      // false only for lane 18
    int  col1  = hasHi ? (col0 + 1) : col0;

    // M: even column (2k) and odd column (2k+1; col 37 -> zeros) as i-pairs
    unsigned long long ME[19], MO[19];
    {
        const unsigned long long* ce =
            (const unsigned long long*)g_Mcol + col0 * 19;
        int oc = hasHi ? (col0 + 1) : 37;
        const unsigned long long* co =
            (const unsigned long long*)g_Mcol + oc * 19;
        #pragma unroll
        for (int k = 0; k < 19; k++) { ME[k] = ce[k]; MO[k] = co[k]; }
    }

    float* qa0 = &qsm[w][0][0][0];
    float* qa1 = &qsm[w][0][1][0];
    float* qb0 = &qsm[w][1][0][0];
    float* qb1 = &qsm[w][1][1][0];

    // zero all four buffers (pads 38,39 stay zero forever)
    for (int x = lane; x < 160; x += 32) (&qsm[w][0][0][0])[x] = 0.0f;

    // chain state registers (current stored q of owned columns)
    float aE, aO, bE, bO;
    if (cA == 0) {
        aE = expf(startt[col0] + eb[col0]);
        aO = hasHi ? expf(startt[col1] + eb[col1]) : 0.0f;
    } else {
        aE = 1.0f; aO = hasHi ? 1.0f : 0.0f;
    }
    bE = 1.0f; bO = hasHi ? 1.0f : 0.0f;
    __syncwarp();
    if (act) {
        *(float2*)(qa0 + col0) = make_float2(aE, aO);
        *(float2*)(qb0 + col0) = make_float2(bE, bO);
    }

    int t0a = cA * CSTEP - (WARM - 1);
    int t0b = cB * CSTEP - (WARM - 1);

    // PF-deep emission/mask prefetch (exp precomputed)
    float eA0[PF], eA1[PF], eB0[PF], eB1[PF];
    int   mmA[PF], mmB[PF];
    if (act) {
        #pragma unroll
        for (int d = 0; d < PF; d++) {
            int ta = t0a + d;
            int tca = ta < 0 ? 0 : (ta >= TLEN ? TLEN - 1 : ta);
            eA0[d] = __expf(eb[(size_t)tca * LSTATE + col0]);
            eA1[d] = hasHi ? __expf(eb[(size_t)tca * LSTATE + col1]) : 0.0f;
            mmA[d] = (ta >= 1 && ta < TLEN) ? mk[tca] : 0;

            int tb = t0b + d;
            int tcb = tb >= TLEN ? TLEN - 1 : tb;
            eB0[d] = __expf(eb[(size_t)tcb * LSTATE + col0]);
            eB1[d] = hasHi ? __expf(eb[(size_t)tcb * LSTATE + col1]) : 0.0f;
            mmB[d] = (tb >= 1 && tb < TLEN) ? mk[tcb] : 0;
        }
    }

    int   kta = 0, ktb = 0;
    float subA = 0.0f, subB = 0.0f;

    for (int g = 0; g < NGROUPS; g++) {
        if (g == WARMG) {   // warm boundary: reference log-mass (no kt reset)
            float va = act ? (aE + aO) : 0.0f;
            float vb = act ? (bE + bO) : 0.0f;
            #pragma unroll
            for (int o = 16; o; o >>= 1) {
                va += __shfl_xor_sync(FULLMASK, va, o);
                vb += __shfl_xor_sync(FULLMASK, vb, o);
            }
            subA = (cA == 0) ? 0.0f
                 : (float)((double)kta * 0.6931471805599453) + logf(va);
            subB = (float)((double)ktb * 0.6931471805599453) + logf(vb);
        }
        #pragma unroll
        for (int u = 0; u < PF; u++) {
            __syncwarp();
            if (act) {
                float evA0 = eA0[u], evA1 = eA1[u];
                float evB0 = eB0[u], evB1 = eB1[u];
                int   mcA = mmA[u],  mcB = mmB[u];
                {   // refill prefetch (off critical path)
                    int ta = t0a + g * PF + u + PF;
                    int tca = ta < 0 ? 0 : (ta >= TLEN ? TLEN - 1 : ta);
                    eA0[u] = __expf(eb[(size_t)tca * LSTATE + col0]);
                    eA1[u] = hasHi ? __expf(eb[(size_t)tca * LSTATE + col1]) : 0.0f;
                    mmA[u] = (ta >= 1 && ta < TLEN) ? mk[tca] : 0;

                    int tb = t0b + g * PF + u + PF;
                    int tcb = tb >= TLEN ? TLEN - 1 : tb;
                    eB0[u] = __expf(eb[(size_t)tcb * LSTATE + col0]);
                    eB1[u] = hasHi ? __expf(eb[(size_t)tcb * LSTATE + col1]) : 0.0f;
                    mmB[u] = (tb >= 1 && tb < TLEN) ? mk[tcb] : 0;
                }

                // ---- chain A ----
                {
                    const float* qr = (u & 1) ? qa1 : qa0;
                    float*       qw = (u & 1) ? qa0 : qa1;
                    const ulonglong2* q16 = (const ulonglong2*)qr;
                    ulonglong2 p0 = q16[0];
                    unsigned long long q18 = ((const unsigned long long*)qr)[18];
                    unsigned long long x0 = 0, x1 = 0, y0 = 0, y1 = 0;
                    fma2(x0, p0.x, ME[0]); fma2(y0, p0.x, MO[0]);
                    fma2(x1, p0.y, ME[1]); fma2(y1, p0.y, MO[1]);
                    #pragma unroll
                    for (int k = 1; k < 9; k++) {
                        ulonglong2 p = q16[k];
                        fma2(x0, p.x, ME[2 * k]);     fma2(y0, p.x, MO[2 * k]);
                        fma2(x1, p.y, ME[2 * k + 1]); fma2(y1, p.y, MO[2 * k + 1]);
                    }
                    fma2(x0, q18, ME[18]); fma2(y0, q18, MO[18]);
                    unsigned long long se = add2(x0, x1), so = add2(y0, y1);
                    float sE = lo32(se) + hi32(se);
                    float sO = lo32(so) + hi32(so);
                    float nE = mcA ? sE * evA0 : aE;
                    float nO = mcA ? sO * evA1 : aO;
                    if (u == PF - 1) {
                        float q0 = lo32(p0.x);
                        unsigned e_ = (__float_as_uint(q0) >> 23) & 0xffu;
                        float scale = __uint_as_float((254u - e_) << 23);
                        kta += (int)e_ - 127;
                        nE *= scale; nO *= scale;
                    }
                    aE = nE; aO = nO;
                    *(float2*)(qw + col0) = make_float2(nE, nO);
                }
                // ---- chain B ----
                {
                    const float* qr = (u & 1) ? qb1 : qb0;
                    float*       qw = (u & 1) ? qb0 : qb1;
                    const ulonglong2* q16 = (const ulonglong2*)qr;
                    ulonglong2 p0 = q16[0];
                    unsigned long long q18 = ((const unsigned long long*)qr)[18];
                    unsigned long long x0 = 0, x1 = 0, y0 = 0, y1 = 0;
                    fma2(x0, p0.x, ME[0]); fma2(y0, p0.x, MO[0]);
                    fma2(x1, p0.y, ME[1]); fma2(y1, p0.y, MO[1]);
                    #pragma unroll
                    for (int k = 1; k < 9; k++) {
                        ulonglong2 p = q16[k];
                        fma2(x0, p.x, ME[2 * k]);     fma2(y0, p.x, MO[2 * k]);
                        fma2(x1, p.y, ME[2 * k + 1]); fma2(y1, p.y, MO[2 * k + 1]);
                    }
                    fma2(x0, q18, ME[18]); fma2(y0, q18, MO[18]);
                    unsigned long long se = add2(x0, x1), so = add2(y0, y1);
                    float sE = lo32(se) + hi32(se);
                    float sO = lo32(so) + hi32(so);
                    float nE = mcB ? sE * evB0 : bE;
                    float nO = mcB ? sO * evB1 : bO;
                    if (u == PF - 1) {
                        float q0 = lo32(p0.x);
                        unsigned e_ = (__float_as_uint(q0) >> 23) & 0xffu;
                        float scale = __uint_as_float((254u - e_) << 23);
                        ktb += (int)e_ - 127;
                        nE *= scale; nO *= scale;
                    }
                    bE = nE; bO = nO;
                    *(float2*)(qw + col0) = make_float2(nE, nO);
                }
            }
        }
    }

    // chunk contributions (ktot*ln2 + log S_end - sub); end weights for c==7
    {
        float va = act ? (aE + aO) : 0.0f;
        float vb;
        if (cB == NCH - 1)
            vb = act ? (bE * expf(endt[col0])
                        + (hasHi ? bO * expf(endt[col1]) : 0.0f)) : 0.0f;
        else
            vb = act ? (bE + bO) : 0.0f;
        #pragma unroll
        for (int o = 16; o; o >>= 1) {
            va += __shfl_xor_sync(FULLMASK, va, o);
            vb += __shfl_xor_sync(FULLMASK, vb, o);
        }
        if (lane == 0) {
            g_chunk[b * NCH + cA] =
                (float)((double)kta * 0.6931471805599453) + logf(va) - subA;
            g_chunk[b * NCH + cB] =
                (float)((double)ktb * 0.6931471805599453) + logf(vb) - subB;
        }
    }

    // ---- fused finish: last block reduces everything ----
    __threadfence();
    __syncthreads();
    if (tid == 0)
        isLast = (atomicAdd(&g_done, 1) == (int)gridDim.x - 1);
    __syncthreads();

    if (isLast) {
        __threadfence();
        float acc = 0.0f; int nt = 0;
        for (int i = tid; i < BATCH; i += 128) {
            float d = 0.0f;
            #pragma unroll
            for (int cc = 0; cc < NCH; cc++) d += g_chunk[i * NCH + cc];
            acc += g_num[i] - d;
            nt  += g_msum[i];
        }
        #pragma unroll
        for (int o = 16; o; o >>= 1) {
            acc += __shfl_xor_sync(FULLMASK, acc, o);
            nt  += __shfl_xor_sync(FULLMASK, nt,  o);
        }
        if (lane == 0) { fr[w] = acc; fn[w] = nt; }
        __syncthreads();
        if (tid == 0) {
            float tot = fr[0] + fr[1] + fr[2] + fr[3];
            int   n   = fn[0] + fn[1] + fn[2] + fn[3];
            if (n < 1) n = 1;
            out[0] = -tot / (float)n;
        }
    }
}

// ---------------------------------------------------------------------------
// Launch
// ---------------------------------------------------------------------------
extern "C" void kernel_launch(void* const* d_in, const int* in_sizes, int n_in,
                              void* d_out, int out_size) {
    const float* em     = (const float*)d_in[0];   // emissions [512,2048,37]
    const float* trans  = (const float*)d_in[1];   // transitions [37,37]
    const float* startt = (const float*)d_in[2];   // start_transitions [37]
    const float* endt   = (const float*)d_in[3];   // end_transitions [37]
    const int*   labels = (const int*)d_in[4];     // labels [512,2048]
    const int*   mask   = (const int*)d_in[5];     // attention_mask [512,2048]

    num_kernel<<<BATCH, 256>>>(em, trans, startt, endt, labels, mask);
    fwd_kernel<<<BATCH * NCH / 8, 128>>>(em, startt, endt, mask, (float*)d_out);
}

// round 11
// speedup vs baseline: 1.5357x; 1.2297x over previous
#include <cuda_runtime.h>
#include <cstdint>
#include <math.h>

// ============================================================================
// CRF token loss: B=512, T=2048, L=37.  loss = -(sum_b num_b - denom_b)/n_tok
// R10: chunked forward (contraction warm-up, numerically verified R8/R9) with
// the shared-memory round-trip replaced by warp broadcast shuffles:
//   s_j = sum_p qpair_p * Mpair[p][j],  qpair_p obtained via __shfl_sync(q, p)
// -> no smem q, no syncwarp, no double buffer; per-step latency ~60 cyc.
// Registers ~125 => __launch_bounds__(128,4) = 16 warps/SM for latency hiding.
// 2048 warps: one warp per (batch, chunk-pair), 2 chains share one M copy.
// ============================================================================

#define LSTATE 37
#define TLEN   2048
#define BATCH  512
#define NCH    8
#define CSTEP  256
#define WARM   16
#define PF     4
#define NGROUPS ((WARM + CSTEP) / PF)   // 68
#define WARMG   (WARM / PF)             // 4
#define FULLMASK 0xffffffffu

// g_Mcol[j][i2] = ( exp(T[2*i2][j]), exp(T[2*i2+1][j]) ); col 37 = zeros,
// i2=18 hi-component = 0 (row-37 padding).
__device__ __align__(16) float2 g_Mcol[38 * 19];
__device__ float g_num[BATCH];
__device__ int   g_msum[BATCH];
__device__ float g_chunk[BATCH * NCH];
__device__ int   g_done;

// ---- f32x2 helpers ---------------------------------------------------------
__device__ __forceinline__ void fma2(unsigned long long& acc,
                                     unsigned long long a, unsigned long long b) {
    asm("fma.rn.f32x2 %0, %1, %2, %0;" : "+l"(acc) : "l"(a), "l"(b));
}
__device__ __forceinline__ unsigned long long add2(unsigned long long a,
                                                   unsigned long long b) {
    unsigned long long c;
    asm("add.rn.f32x2 %0, %1, %2;" : "=l"(c) : "l"(a), "l"(b));
    return c;
}
__device__ __forceinline__ float lo32(unsigned long long v) {
    return __uint_as_float((unsigned)v);
}
__device__ __forceinline__ float hi32(unsigned long long v) {
    return __uint_as_float((unsigned)(v >> 32));
}
__device__ __forceinline__ unsigned long long pack2(float lo, float hi) {
    return (unsigned long long)__float_as_uint(lo)
         | ((unsigned long long)__float_as_uint(hi) << 32);
}

// ---------------------------------------------------------------------------
// Kernel 1: numerator, one block per batch; block 0 also preps M columns
// ---------------------------------------------------------------------------
__global__ void num_kernel(const float* __restrict__ em,
                           const float* __restrict__ trans,
                           const float* __restrict__ startt,
                           const float* __restrict__ endt,
                           const int*   __restrict__ labels,
                           const int*   __restrict__ mask) {
    int b = blockIdx.x, tid = threadIdx.x;
    if (b == 0) {
        for (int x = tid; x < 38 * 19; x += 256) {
            int j = x / 19, i2 = x % 19;
            float lo = 0.0f, hi = 0.0f;
            if (j < LSTATE) {
                lo = expf(trans[(2 * i2) * LSTATE + j]);
                if (2 * i2 + 1 < LSTATE)
                    hi = expf(trans[(2 * i2 + 1) * LSTATE + j]);
            }
            g_Mcol[x] = make_float2(lo, hi);
        }
        if (tid == 0) g_done = 0;
    }

    __shared__ float sacc[8];
    __shared__ int   snt[8];
    const int*   lb = labels + (size_t)b * TLEN;
    const int*   mk = mask   + (size_t)b * TLEN;
    const float* eb = em     + (size_t)b * TLEN * LSTATE;

    float acc = 0.0f; int msum = 0;
    for (int t = tid; t < TLEN; t += 256) {
        int lt = lb[t]; int m = mk[t]; msum += m;
        if (t == 0) acc += startt[lt] + eb[lt];
        else if (m) acc += trans[lb[t - 1] * LSTATE + lt]
                         + eb[(size_t)t * LSTATE + lt];
    }
    int lane = tid & 31, wid = tid >> 5;
    #pragma unroll
    for (int o = 16; o; o >>= 1) {
        acc  += __shfl_xor_sync(FULLMASK, acc,  o);
        msum += __shfl_xor_sync(FULLMASK, msum, o);
    }
    if (lane == 0) { sacc[wid] = acc; snt[wid] = msum; }
    __syncthreads();
    if (tid == 0) {
        float a = 0.0f; int n = 0;
        #pragma unroll
        for (int k = 0; k < 8; k++) { a += sacc[k]; n += snt[k]; }
        g_num[b]  = a + endt[lb[n - 1]];
        g_msum[b] = n;
    }
}

// ---------------------------------------------------------------------------
// Kernel 2: chunked forward, shuffle-broadcast matvec, no smem in the loop.
// One warp per chunk pair; 4 warps/block; grid 512.
// ---------------------------------------------------------------------------
__global__ void __launch_bounds__(128, 4)
fwd_kernel(const float* __restrict__ em,
           const float* __restrict__ startt,
           const float* __restrict__ endt,
           const int*   __restrict__ mask,
           float* __restrict__ out) {
    __shared__ float fr[4];
    __shared__ int   fn[4];
    __shared__ int   isLast;

    int tid  = threadIdx.x;
    int lane = tid & 31;
    int w    = tid >> 5;
    int wt   = blockIdx.x * 4 + w;      // 0..2047
    int b    = wt >> 2;
    int cA   = (wt & 3) * 2;
    int cB   = cA + 1;

    const float* eb = em   + (size_t)b * TLEN * LSTATE;
    const int*   mk = mask + (size_t)b * TLEN;

    bool act   = (lane < 19);
    int  kc    = act ? lane : 18;
    int  col0  = 2 * kc;
    bool hasHi = (col0 + 1 < LSTATE);        // false only for lane 18
    int  col1  = hasHi ? (col0 + 1) : col0;

    // M: even and odd column of this lane, as i-pairs (odd col 37 -> zeros)
    unsigned long long ME[19], MO[19];
    {
        const unsigned long long* ce =
            (const unsigned long long*)g_Mcol + col0 * 19;
        int oc = hasHi ? (col0 + 1) : 37;
        const unsigned long long* co =
            (const unsigned long long*)g_Mcol + oc * 19;
        #pragma unroll
        for (int k = 0; k < 19; k++) { ME[k] = ce[k]; MO[k] = co[k]; }
    }

    // chain states: packed (q_even, q_odd), live in registers only
    unsigned long long qA, qB;
    if (cA == 0) {
        float aE = expf(startt[col0] + eb[col0]);
        float aO = hasHi ? expf(startt[col1] + eb[col1]) : 0.0f;
        qA = pack2(aE, aO);
    } else {
        qA = pack2(1.0f, hasHi ? 1.0f : 0.0f);
    }
    qB = pack2(1.0f, hasHi ? 1.0f : 0.0f);

    int t0a = cA * CSTEP - (WARM - 1);
    const float* ebc0 = eb + col0;
    const float* ebc1 = eb + col1;

    // PF-slot prefetch: exp(emission pair) packed; masks as bitfields
    unsigned long long eeA[PF], eeB[PF];
    unsigned mA = 0, mB = 0;
    #pragma unroll
    for (int d = 0; d < PF; d++) {
        int ta  = t0a + d;
        int tca = ta < 0 ? 0 : (ta >= TLEN ? TLEN - 1 : ta);
        eeA[d] = pack2(__expf(ebc0[(size_t)tca * LSTATE]),
                       hasHi ? __expf(ebc1[(size_t)tca * LSTATE]) : 0.0f);
        mA |= ((ta >= 1 && ta < TLEN) ? (mk[tca] & 1) : 0) << d;

        int tb  = ta + CSTEP;
        int tcb = tb >= TLEN ? TLEN - 1 : tb;
        eeB[d] = pack2(__expf(ebc0[(size_t)tcb * LSTATE]),
                       hasHi ? __expf(ebc1[(size_t)tcb * LSTATE]) : 0.0f);
        mB |= ((tb >= 1 && tb < TLEN) ? (mk[tcb] & 1) : 0) << d;
    }

    int   kta = 0, ktb = 0;
    float subA = 0.0f, subB = 0.0f;

    for (int g = 0; g < NGROUPS; g++) {
        if (g == WARMG) {   // warm boundary: reference log-mass (no kt reset)
            float va = act ? (lo32(qA) + hi32(qA)) : 0.0f;
            float vb = act ? (lo32(qB) + hi32(qB)) : 0.0f;
            #pragma unroll
            for (int o = 16; o; o >>= 1) {
                va += __shfl_xor_sync(FULLMASK, va, o);
                vb += __shfl_xor_sync(FULLMASK, vb, o);
            }
            subA = (cA == 0) ? 0.0f
                 : (float)((double)kta * 0.6931471805599453) + logf(va);
            subB = (float)((double)ktb * 0.6931471805599453) + logf(vb);
        }
        #pragma unroll
        for (int u = 0; u < PF; u++) {
            unsigned long long eA = eeA[u], eB2 = eeB[u];
            int mcA = (mA >> u) & 1, mcB = (mB >> u) & 1;

            {   // refill slot u for t + PF (off critical path)
                int ta  = t0a + g * PF + u + PF;
                int tca = ta < 0 ? 0 : (ta >= TLEN ? TLEN - 1 : ta);
                eeA[u] = pack2(__expf(ebc0[(size_t)tca * LSTATE]),
                               hasHi ? __expf(ebc1[(size_t)tca * LSTATE]) : 0.0f);
                unsigned bA = (ta >= 1 && ta < TLEN) ? (mk[tca] & 1) : 0;
                mA = (mA & ~(1u << u)) | (bA << u);

                int tb  = ta + CSTEP;
                int tcb = tb >= TLEN ? TLEN - 1 : tb;
                eeB[u] = pack2(__expf(ebc0[(size_t)tcb * LSTATE]),
                               hasHi ? __expf(ebc1[(size_t)tcb * LSTATE]) : 0.0f);
                unsigned bB = (tb >= 1 && tb < TLEN) ? (mk[tcb] & 1) : 0;
                mB = (mB & ~(1u << u)) | (bB << u);
            }

            // ---- matvec for both chains via warp broadcasts ----
            unsigned long long aE0 = 0, aE1 = 0, aO0 = 0, aO1 = 0;
            unsigned long long bE0 = 0, bE1 = 0, bO0 = 0, bO1 = 0;
            float q0A = 0.0f, q0B = 0.0f;
            #pragma unroll
            for (int r = 0; r < 19; r++) {
                unsigned long long va = __shfl_sync(FULLMASK, qA, r);
                unsigned long long vb = __shfl_sync(FULLMASK, qB, r);
                if (r == 0) { q0A = lo32(va); q0B = lo32(vb); }
                if (r & 1) {
                    fma2(aE1, va, ME[r]); fma2(aO1, va, MO[r]);
                    fma2(bE1, vb, ME[r]); fma2(bO1, vb, MO[r]);
                } else {
                    fma2(aE0, va, ME[r]); fma2(aO0, va, MO[r]);
                    fma2(bE0, vb, ME[r]); fma2(bO0, vb, MO[r]);
                }
            }
            unsigned long long sae = add2(aE0, aE1), sao = add2(aO0, aO1);
            unsigned long long sbe = add2(bE0, bE1), sbo = add2(bO0, bO1);
            float sAE = lo32(sae) + hi32(sae);
            float sAO = lo32(sao) + hi32(sao);
            float sBE = lo32(sbe) + hi32(sbe);
            float sBO = lo32(sbo) + hi32(sbo);

            float nAE = mcA ? sAE * lo32(eA)  : lo32(qA);
            float nAO = mcA ? sAO * hi32(eA)  : hi32(qA);
            float nBE = mcB ? sBE * lo32(eB2) : lo32(qB);
            float nBO = mcB ? sBO * hi32(eB2) : hi32(qB);

            if (u == PF - 1) {   // exact power-of-2 renorm every PF steps
                unsigned ea_ = (__float_as_uint(q0A) >> 23) & 0xffu;
                float scA = __uint_as_float((254u - ea_) << 23);
                kta += (int)ea_ - 127;
                nAE *= scA; nAO *= scA;
                unsigned eb_ = (__float_as_uint(q0B) >> 23) & 0xffu;
                float scB = __uint_as_float((254u - eb_) << 23);
                ktb += (int)eb_ - 127;
                nBE *= scB; nBO *= scB;
            }
            qA = pack2(nAE, nAO);
            qB = pack2(nBE, nBO);
        }
    }

    // chunk contributions (ktot*ln2 + log S_end - sub); end weights for c==7
    {
        float va = act ? (lo32(qA) + hi32(qA)) : 0.0f;
        float vb;
        if (cB == NCH - 1)
            vb = act ? (lo32(qB) * expf(endt[col0])
                        + (hasHi ? hi32(qB) * expf(endt[col1]) : 0.0f)) : 0.0f;
        else
            vb = act ? (lo32(qB) + hi32(qB)) : 0.0f;
        #pragma unroll
        for (int o = 16; o; o >>= 1) {
            va += __shfl_xor_sync(FULLMASK, va, o);
            vb += __shfl_xor_sync(FULLMASK, vb, o);
        }
        if (lane == 0) {
            g_chunk[b * NCH + cA] =
                (float)((double)kta * 0.6931471805599453) + logf(va) - subA;
            g_chunk[b * NCH + cB] =
                (float)((double)ktb * 0.6931471805599453) + logf(vb) - subB;
        }
    }

    // ---- fused finish: last block reduces everything ----
    __threadfence();
    __syncthreads();
    if (tid == 0)
        isLast = (atomicAdd(&g_done, 1) == (int)gridDim.x - 1);
    __syncthreads();

    if (isLast) {
        __threadfence();
        float acc = 0.0f; int nt = 0;
        for (int i = tid; i < BATCH; i += 128) {
            float d = 0.0f;
            #pragma unroll
            for (int cc = 0; cc < NCH; cc++) d += g_chunk[i * NCH + cc];
            acc += g_num[i] - d;
            nt  += g_msum[i];
        }
        #pragma unroll
        for (int o = 16; o; o >>= 1) {
            acc += __shfl_xor_sync(FULLMASK, acc, o);
            nt  += __shfl_xor_sync(FULLMASK, nt,  o);
        }
        if (lane == 0) { fr[w] = acc; fn[w] = nt; }
        __syncthreads();
        if (tid == 0) {
            float tot = fr[0] + fr[1] + fr[2] + fr[3];
            int   n   = fn[0] + fn[1] + fn[2] + fn[3];
            if (n < 1) n = 1;
            out[0] = -tot / (float)n;
        }
    }
}

// ---------------------------------------------------------------------------
// Launch
// ---------------------------------------------------------------------------
extern "C" void kernel_launch(void* const* d_in, const int* in_sizes, int n_in,
                              void* d_out, int out_size) {
    const float* em     = (const float*)d_in[0];   // emissions [512,2048,37]
    const float* trans  = (const float*)d_in[1];   // transitions [37,37]
    const float* startt = (const float*)d_in[2];   // start_transitions [37]
    const float* endt   = (const float*)d_in[3];   // end_transitions [37]
    const int*   labels = (const int*)d_in[4];     // labels [512,2048]
    const int*   mask   = (const int*)d_in[5];     // attention_mask [512,2048]

    num_kernel<<<BATCH, 256>>>(em, trans, startt, endt, labels, mask);
    fwd_kernel<<<BATCH * NCH / 8, 128>>>(em, startt, endt, mask, (float*)d_out);
}